// round 1
// baseline (speedup 1.0000x reference)
#include <cuda_runtime.h>
#include <math.h>

#define N       300
#define NM      9
#define BATCH   131072
#define NLAYERS 5
#define KTAP    12
#define TAPS    (2*KTAP + 1)   // 25
#define WIN     (10 + 2*KTAP)  // 34
#define PADN    320
#define AHS     12             // padded row stride (floats) for A / H tables
#define WARPS   8
#define RPW     16             // rows per warp
#define FULLMASK 0xffffffffu

static __device__ double g_cfull[NLAYERS][N];
static __device__ float  g_G[NLAYERS][NM * N];
static __device__ float  g_AH[PADN * AHS];
static __device__ float  g_H[NLAYERS][PADN * AHS];
static __device__ float  g_ct[NLAYERS][28];
static __device__ float  g_scal[NLAYERS][8];

// ---------------------------------------------------------------------------
// Precompute 1: runtime layout of A: g_AH[j][m] = A[m][j], zero-padded.
// ---------------------------------------------------------------------------
__global__ void pre_A_kernel(const float* __restrict__ A) {
    int idx = blockIdx.x * blockDim.x + threadIdx.x;
    if (idx < PADN * AHS) {
        int j = idx / AHS, m = idx % AHS;
        g_AH[idx] = (j < N && m < NM) ? A[m * N + j] : 0.0f;
    }
}

// ---------------------------------------------------------------------------
// Precompute 2 (per layer block): circulant inverse c, G = A C^-1,
// S9 = I + A C^-1 A^T, S9^-1 (9x9 GJ), H = S9^-1 G, conv taps, scalars.
// ---------------------------------------------------------------------------
__global__ void pre_layer_kernel(const float* __restrict__ A,
                                 const float* __restrict__ gamma_tv,
                                 const float* __restrict__ lambda_tv,
                                 const float* __restrict__ alpha) {
    const double PI = 3.14159265358979323846;
    int l = blockIdx.x;
    int tid = threadIdx.x;
    double g = (double)gamma_tv[l], al = (double)alpha[l];

    __shared__ double costab[N];
    __shared__ double invlam[N];
    for (int m = tid; m < N; m += blockDim.x) {
        double th = 2.0 * PI * (double)m / (double)N;
        double cs = cos(th);
        costab[m] = cs;
        invlam[m] = 1.0 / (al + 2.0 * g - 2.0 * g * cs);
    }
    __syncthreads();

    // c[k] = (1/N) sum_m cos(2*pi*m*k/N) / lambda_m
    for (int k = tid; k < N; k += blockDim.x) {
        double s = 0.0;
        int mk = 0;
        for (int m = 0; m < N; m++) {
            s += costab[mk] * invlam[m];
            mk += k; if (mk >= N) mk -= N;
        }
        g_cfull[l][k] = s / (double)N;
    }
    __syncthreads();

    // G[m][j] = sum_t A[m][t] * c[(j - t) mod N]
    for (int idx = tid; idx < NM * N; idx += blockDim.x) {
        int m = idx / N, j = idx % N;
        float s = 0.f;
        for (int t = 0; t < N; t++) {
            int d = j - t; if (d < 0) d += N;
            s += A[m * N + t] * (float)g_cfull[l][d];
        }
        g_G[l][m * N + j] = s;
    }
    __syncthreads();

    __shared__ double S9[81], S9i[81];
    for (int idx = tid; idx < 81; idx += blockDim.x) {
        int p = idx / 9, q = idx % 9;
        double s = (p == q) ? 1.0 : 0.0;
        for (int j = 0; j < N; j++)
            s += (double)g_G[l][p * N + j] * (double)A[q * N + j];
        S9[idx] = s;
    }
    __syncthreads();

    if (tid == 0) {
        for (int i = 0; i < 81; i++) S9i[i] = ((i / 9) == (i % 9)) ? 1.0 : 0.0;
        for (int col = 0; col < 9; col++) {
            int piv = col; double best = fabs(S9[col * 9 + col]);
            for (int rr = col + 1; rr < 9; rr++) {
                double v = fabs(S9[rr * 9 + col]);
                if (v > best) { best = v; piv = rr; }
            }
            if (piv != col) {
                for (int c2 = 0; c2 < 9; c2++) {
                    double tmp = S9[col * 9 + c2]; S9[col * 9 + c2] = S9[piv * 9 + c2]; S9[piv * 9 + c2] = tmp;
                    tmp = S9i[col * 9 + c2]; S9i[col * 9 + c2] = S9i[piv * 9 + c2]; S9i[piv * 9 + c2] = tmp;
                }
            }
            double d = 1.0 / S9[col * 9 + col];
            for (int c2 = 0; c2 < 9; c2++) { S9[col * 9 + c2] *= d; S9i[col * 9 + c2] *= d; }
            for (int rr = 0; rr < 9; rr++) {
                if (rr == col) continue;
                double f = S9[rr * 9 + col];
                for (int c2 = 0; c2 < 9; c2++) {
                    S9[rr * 9 + c2]  -= f * S9[col * 9 + c2];
                    S9i[rr * 9 + c2] -= f * S9i[col * 9 + c2];
                }
            }
        }
    }
    __syncthreads();

    // H[p][j] = sum_q S9i[p][q] * G[q][j], stored [j][p] padded
    for (int idx = tid; idx < PADN * AHS; idx += blockDim.x) {
        int j = idx / AHS, p = idx % AHS;
        float s = 0.f;
        if (j < N && p < NM) {
            for (int q = 0; q < NM; q++)
                s += (float)S9i[p * 9 + q] * g_G[l][q * N + j];
        }
        g_H[l][idx] = s;
    }
    // symmetric conv taps ct[i] = c[|i - K|]
    for (int i = tid; i < 28; i += blockDim.x) {
        float v = 0.f;
        if (i < TAPS) { int d = i - KTAP; if (d < 0) d = -d; v = (float)g_cfull[l][d]; }
        g_ct[l][i] = v;
    }
    if (tid == 0) {
        g_scal[l][0] = (float)g;
        g_scal[l][1] = (float)al;
        g_scal[l][2] = (float)((double)lambda_tv[l] / g);
        g_scal[l][3] = (float)(1.0 / g);
        g_scal[l][4] = (float)(1.0 / al);
    }
}

// ---------------------------------------------------------------------------
// Main fused kernel: one warp per batch row, all state register-resident.
// Lane L (0..29) owns elements j = 10L .. 10L+9 of the length-300 row.
// ---------------------------------------------------------------------------
__global__ void __launch_bounds__(WARPS * 32)
ladmm_main(const float* __restrict__ b, float* __restrict__ out) {
    extern __shared__ float sm[];
    float* sAH   = sm;                                // PADN*AHS
    float* sH    = sAH + PADN * AHS;                  // NLAYERS*PADN*AHS
    float* sct   = sH + NLAYERS * PADN * AHS;         // NLAYERS*28
    float* sscal = sct + NLAYERS * 28;                // NLAYERS*8
    float* stage = sscal + NLAYERS * 8;               // WARPS*304

    int tid = threadIdx.x;
    for (int i = tid; i < PADN * AHS; i += WARPS * 32) sAH[i] = g_AH[i];
    for (int i = tid; i < NLAYERS * PADN * AHS; i += WARPS * 32) sH[i] = (&g_H[0][0])[i];
    for (int i = tid; i < NLAYERS * 28; i += WARPS * 32) sct[i] = (&g_ct[0][0])[i];
    for (int i = tid; i < NLAYERS * 8; i += WARPS * 32) sscal[i] = (&g_scal[0][0])[i];
    __syncthreads();

    int wid = tid >> 5, lane = tid & 31;
    int j0  = lane * 10;                    // lanes 30/31 index zero pad rows
    int lm2 = (lane + 28) % 30;
    int lm1 = (lane + 29) % 30;
    int lp1 = (lane + 1) % 30;
    int lp2 = (lane + 2) % 30;

    const float4* sAH4 = reinterpret_cast<const float4*>(sAH);

    for (int rit = 0; rit < RPW; rit++) {
        int row = blockIdx.x * (WARPS * RPW) + wid * RPW + rit;

        // b row -> broadcast; bA[j] = sum_m b[m] * A[m][j]
        float bv = (lane < NM) ? b[(size_t)row * NM + lane] : 0.f;
        float bm[9];
        #pragma unroll
        for (int m = 0; m < 9; m++) bm[m] = __shfl_sync(FULLMASK, bv, m);
        float bA[10];
        #pragma unroll
        for (int t = 0; t < 10; t++) {
            float4 a0 = sAH4[(j0 + t) * 3 + 0];
            float4 a1 = sAH4[(j0 + t) * 3 + 1];
            float4 a2 = sAH4[(j0 + t) * 3 + 2];
            bA[t] = a0.x * bm[0] + a0.y * bm[1] + a0.z * bm[2] + a0.w * bm[3]
                  + a1.x * bm[4] + a1.y * bm[5] + a1.z * bm[6] + a1.w * bm[7]
                  + a2.x * bm[8];
        }

        float x[10], eta[10], tau[10];
        #pragma unroll
        for (int t = 0; t < 10; t++) { x[t] = 1.f; eta[t] = 0.f; tau[t] = 0.f; }

        for (int l = 0; l < NLAYERS; l++) {
            const float* sc = sscal + l * 8;
            float g = sc[0], al = sc[1], lamg = sc[2], invg = sc[3], inval = sc[4];

            float xm1 = __shfl_sync(FULLMASK, x[9], lm1);
            float r[10];
            #pragma unroll
            for (int t = 0; t < 10; t++) {
                float xp = (t == 0) ? xm1 : x[t - 1];
                float v  = (xp - x[t]) + eta[t] * invg;
                float u  = fmaxf(fabsf(v) - lamg, 0.f);
                u = (v < 0.f) ? -u : u;
                float w = fmaxf(x[t] + tau[t] * inval, 0.f);
                r[t] = bA[t] + al * w - tau[t] + g * u - eta[t];
            }

            // halo exchange: window r[j0-12 .. j0+21] (circular mod 300)
            float win[WIN];
            win[0] = __shfl_sync(FULLMASK, r[8], lm2);
            win[1] = __shfl_sync(FULLMASK, r[9], lm2);
            #pragma unroll
            for (int i = 0; i < 10; i++) win[2 + i]  = __shfl_sync(FULLMASK, r[i], lm1);
            #pragma unroll
            for (int t = 0; t < 10; t++) win[12 + t] = r[t];
            #pragma unroll
            for (int i = 0; i < 10; i++) win[22 + i] = __shfl_sync(FULLMASK, r[i], lp1);
            win[32] = __shfl_sync(FULLMASK, r[0], lp2);
            win[33] = __shfl_sync(FULLMASK, r[1], lp2);

            // y = C^-1 r  (25-tap symmetric circulant conv)
            float y[10];
            #pragma unroll
            for (int t = 0; t < 10; t++) y[t] = 0.f;
            const float* ct = sct + l * 28;
            #pragma unroll
            for (int i = 0; i < TAPS; i++) {
                float ci = ct[i];
                #pragma unroll
                for (int t = 0; t < 10; t++) y[t] = fmaf(ci, win[t + i], y[t]);
            }

            // d9[m] = sum_j y[j] * A[m][j]  (warp reduction)
            float pd[9];
            #pragma unroll
            for (int m = 0; m < 9; m++) pd[m] = 0.f;
            #pragma unroll
            for (int t = 0; t < 10; t++) {
                float4 a0 = sAH4[(j0 + t) * 3 + 0];
                float4 a1 = sAH4[(j0 + t) * 3 + 1];
                float4 a2 = sAH4[(j0 + t) * 3 + 2];
                float yt = y[t];
                pd[0] = fmaf(yt, a0.x, pd[0]); pd[1] = fmaf(yt, a0.y, pd[1]);
                pd[2] = fmaf(yt, a0.z, pd[2]); pd[3] = fmaf(yt, a0.w, pd[3]);
                pd[4] = fmaf(yt, a1.x, pd[4]); pd[5] = fmaf(yt, a1.y, pd[5]);
                pd[6] = fmaf(yt, a1.z, pd[6]); pd[7] = fmaf(yt, a1.w, pd[7]);
                pd[8] = fmaf(yt, a2.x, pd[8]);
            }
            #pragma unroll
            for (int m = 0; m < 9; m++) {
                #pragma unroll
                for (int off = 16; off >= 1; off >>= 1)
                    pd[m] += __shfl_xor_sync(FULLMASK, pd[m], off);
            }

            // x_new = y - d9 . H   (Woodbury rank-9 correction)
            const float4* sH4 = reinterpret_cast<const float4*>(sH + l * PADN * AHS);
            float xn[10];
            #pragma unroll
            for (int t = 0; t < 10; t++) {
                float4 h0 = sH4[(j0 + t) * 3 + 0];
                float4 h1 = sH4[(j0 + t) * 3 + 1];
                float4 h2 = sH4[(j0 + t) * 3 + 2];
                float acc = pd[0] * h0.x + pd[1] * h0.y + pd[2] * h0.z + pd[3] * h0.w
                          + pd[4] * h1.x + pd[5] * h1.y + pd[6] * h1.z + pd[7] * h1.w
                          + pd[8] * h2.x;
                xn[t] = y[t] - acc;
            }

            // dual updates (recompute u, w from OLD state)
            float xnm1 = __shfl_sync(FULLMASK, xn[9], lm1);
            #pragma unroll
            for (int t = 0; t < 10; t++) {
                float xp  = (t == 0) ? xm1  : x[t - 1];
                float xnp = (t == 0) ? xnm1 : xn[t - 1];
                float v = (xp - x[t]) + eta[t] * invg;
                float u = fmaxf(fabsf(v) - lamg, 0.f);
                u = (v < 0.f) ? -u : u;
                float w = fmaxf(x[t] + tau[t] * inval, 0.f);
                eta[t] = fmaf(g, (xnp - xn[t]) - u, eta[t]);
                tau[t] = fmaf(al, xn[t] - w, tau[t]);
            }
            #pragma unroll
            for (int t = 0; t < 10; t++) x[t] = xn[t];
        }

        // coalesced store via smem staging
        if (lane < 30) {
            #pragma unroll
            for (int t = 0; t < 10; t++) stage[wid * 304 + j0 + t] = x[t];
        }
        __syncwarp();
        for (int idx = lane; idx < N; idx += 32)
            out[(size_t)row * N + idx] = stage[wid * 304 + idx];
        __syncwarp();
    }
}

// ---------------------------------------------------------------------------
extern "C" void kernel_launch(void* const* d_in, const int* in_sizes, int n_in,
                              void* d_out, int out_size) {
    const float* b         = (const float*)d_in[0];
    // d_in[1] = target (only its shape matters; x0 = ones)
    const float* A         = (const float*)d_in[2];
    const float* gamma_tv  = (const float*)d_in[3];
    const float* lambda_tv = (const float*)d_in[4];
    const float* alpha     = (const float*)d_in[5];
    float* out = (float*)d_out;

    pre_A_kernel<<<(PADN * AHS + 255) / 256, 256>>>(A);
    pre_layer_kernel<<<NLAYERS, 256>>>(A, gamma_tv, lambda_tv, alpha);

    size_t smembytes = (size_t)(PADN * AHS * (1 + NLAYERS)
                                + NLAYERS * 28 + NLAYERS * 8
                                + WARPS * 304) * sizeof(float);
    cudaFuncSetAttribute(ladmm_main,
                         cudaFuncAttributeMaxDynamicSharedMemorySize,
                         (int)smembytes);
    ladmm_main<<<BATCH / (WARPS * RPW), WARPS * 32, smembytes>>>(b, out);
}

// round 2
// speedup vs baseline: 1.4707x; 1.4707x over previous
#include <cuda_runtime.h>
#include <math.h>

#define N       300
#define NM      9
#define BATCH   131072
#define NLAYERS 5
#define KTAP    10
#define TAPS    (2*KTAP + 1)   // 21
#define TBL     416            // table length: lane*13 + t, lanes 0..31
#define WARPS   8
#define RPW     8              // row-PAIRS per warp
#define FULLMASK 0xffffffffu

static __device__ double g_cfull[NLAYERS][N];
static __device__ float  g_G[NLAYERS][NM * N];
static __device__ float  g_At[NM * TBL];             // A[m][j] at [m][13L+t], j=10L+t
static __device__ float  g_Hn[NLAYERS][NM * TBL];    // NEGATED H, same layout
static __device__ float  g_ct[NLAYERS][24];          // conv taps ct[i]=c[|i-10|]
static __device__ float  g_scal[NLAYERS][8];

// ---------------------------------------------------------------------------
// packed f32x2 helpers (sm_103a)
// ---------------------------------------------------------------------------
__device__ __forceinline__ float2 f2fma(float2 a, float2 b, float2 c) {
    unsigned long long ra = reinterpret_cast<unsigned long long&>(a);
    unsigned long long rb = reinterpret_cast<unsigned long long&>(b);
    unsigned long long rc = reinterpret_cast<unsigned long long&>(c);
    unsigned long long rd;
    asm("fma.rn.f32x2 %0, %1, %2, %3;" : "=l"(rd) : "l"(ra), "l"(rb), "l"(rc));
    return reinterpret_cast<float2&>(rd);
}
__device__ __forceinline__ float2 f2add(float2 a, float2 b) {
    unsigned long long ra = reinterpret_cast<unsigned long long&>(a);
    unsigned long long rb = reinterpret_cast<unsigned long long&>(b);
    unsigned long long rd;
    asm("add.rn.f32x2 %0, %1, %2;" : "=l"(rd) : "l"(ra), "l"(rb));
    return reinterpret_cast<float2&>(rd);
}
__device__ __forceinline__ float2 f2mul(float2 a, float2 b) {
    unsigned long long ra = reinterpret_cast<unsigned long long&>(a);
    unsigned long long rb = reinterpret_cast<unsigned long long&>(b);
    unsigned long long rd;
    asm("mul.rn.f32x2 %0, %1, %2;" : "=l"(rd) : "l"(ra), "l"(rb));
    return reinterpret_cast<float2&>(rd);
}
__device__ __forceinline__ float2 dup(float s) { return make_float2(s, s); }
__device__ __forceinline__ float2 shfl2(float2 v, int src) {
    float2 r;
    r.x = __shfl_sync(FULLMASK, v.x, src);
    r.y = __shfl_sync(FULLMASK, v.y, src);
    return r;
}
__device__ __forceinline__ float2 bfly_sum(float2 v) {
    #pragma unroll
    for (int off = 16; off >= 1; off >>= 1) {
        float sx = __shfl_xor_sync(FULLMASK, v.x, off);
        float sy = __shfl_xor_sync(FULLMASK, v.y, off);
        v = f2add(v, make_float2(sx, sy));
    }
    return v;
}
__device__ __forceinline__ float softt(float v, float lam) {
    return copysignf(fmaxf(fabsf(v) - lam, 0.f), v);
}

// ---------------------------------------------------------------------------
// Precompute: A transposed conflict-free table
// ---------------------------------------------------------------------------
__global__ void pre_A_kernel(const float* __restrict__ A) {
    int idx = blockIdx.x * blockDim.x + threadIdx.x;
    if (idx < NM * TBL) {
        int m = idx / TBL, ii = idx % TBL;
        int L = ii / 13, t = ii % 13;
        int j = L * 10 + t;
        g_At[idx] = (t < 10 && j < N) ? A[m * N + j] : 0.0f;
    }
}

// ---------------------------------------------------------------------------
// Precompute per layer: circulant inverse c, G=A C^-1, S9^-1, Hn=-S9i G, taps
// ---------------------------------------------------------------------------
__global__ void pre_layer_kernel(const float* __restrict__ A,
                                 const float* __restrict__ gamma_tv,
                                 const float* __restrict__ lambda_tv,
                                 const float* __restrict__ alpha) {
    const double PI = 3.14159265358979323846;
    int l = blockIdx.x;
    int tid = threadIdx.x;
    double g = (double)gamma_tv[l], al = (double)alpha[l];

    __shared__ double costab[N];
    __shared__ double invlam[N];
    for (int m = tid; m < N; m += blockDim.x) {
        double th = 2.0 * PI * (double)m / (double)N;
        costab[m] = cos(th);
        invlam[m] = 1.0 / (al + 2.0 * g - 2.0 * g * costab[m]);
    }
    __syncthreads();

    for (int k = tid; k < N; k += blockDim.x) {
        double s = 0.0;
        int mk = 0;
        for (int m = 0; m < N; m++) {
            s += costab[mk] * invlam[m];
            mk += k; if (mk >= N) mk -= N;
        }
        g_cfull[l][k] = s / (double)N;
    }
    __syncthreads();

    for (int idx = tid; idx < NM * N; idx += blockDim.x) {
        int m = idx / N, j = idx % N;
        float s = 0.f;
        for (int t = 0; t < N; t++) {
            int d = j - t; if (d < 0) d += N;
            s += A[m * N + t] * (float)g_cfull[l][d];
        }
        g_G[l][m * N + j] = s;
    }
    __syncthreads();

    __shared__ double S9[81], S9i[81];
    for (int idx = tid; idx < 81; idx += blockDim.x) {
        int p = idx / 9, q = idx % 9;
        double s = (p == q) ? 1.0 : 0.0;
        for (int j = 0; j < N; j++)
            s += (double)g_G[l][p * N + j] * (double)A[q * N + j];
        S9[idx] = s;
    }
    __syncthreads();

    if (tid == 0) {
        for (int i = 0; i < 81; i++) S9i[i] = ((i / 9) == (i % 9)) ? 1.0 : 0.0;
        for (int col = 0; col < 9; col++) {
            int piv = col; double best = fabs(S9[col * 9 + col]);
            for (int rr = col + 1; rr < 9; rr++) {
                double v = fabs(S9[rr * 9 + col]);
                if (v > best) { best = v; piv = rr; }
            }
            if (piv != col) {
                for (int c2 = 0; c2 < 9; c2++) {
                    double tmp = S9[col * 9 + c2]; S9[col * 9 + c2] = S9[piv * 9 + c2]; S9[piv * 9 + c2] = tmp;
                    tmp = S9i[col * 9 + c2]; S9i[col * 9 + c2] = S9i[piv * 9 + c2]; S9i[piv * 9 + c2] = tmp;
                }
            }
            double d = 1.0 / S9[col * 9 + col];
            for (int c2 = 0; c2 < 9; c2++) { S9[col * 9 + c2] *= d; S9i[col * 9 + c2] *= d; }
            for (int rr = 0; rr < 9; rr++) {
                if (rr == col) continue;
                double f = S9[rr * 9 + col];
                for (int c2 = 0; c2 < 9; c2++) {
                    S9[rr * 9 + c2]  -= f * S9[col * 9 + c2];
                    S9i[rr * 9 + c2] -= f * S9i[col * 9 + c2];
                }
            }
        }
    }
    __syncthreads();

    // Hn[m][13L+t] = - sum_q S9i[m][q] * G[q][j],  j = 10L+t
    for (int idx = tid; idx < NM * TBL; idx += blockDim.x) {
        int m = idx / TBL, ii = idx % TBL;
        int L = ii / 13, t = ii % 13;
        int j = L * 10 + t;
        float s = 0.f;
        if (t < 10 && j < N) {
            for (int q = 0; q < NM; q++)
                s -= (float)S9i[m * 9 + q] * g_G[l][q * N + j];
        }
        g_Hn[l][idx] = s;
    }
    for (int i = tid; i < 24; i += blockDim.x) {
        float v = 0.f;
        if (i < TAPS) { int d = i - KTAP; if (d < 0) d = -d; v = (float)g_cfull[l][d]; }
        g_ct[l][i] = v;
    }
    if (tid == 0) {
        g_scal[l][0] = (float)g;
        g_scal[l][1] = (float)al;
        g_scal[l][2] = (float)((double)lambda_tv[l] / g);
        g_scal[l][3] = (float)(1.0 / g);
        g_scal[l][4] = (float)(1.0 / al);
    }
}

// ---------------------------------------------------------------------------
// Main fused kernel: one warp per PAIR of batch rows (f32x2 packed).
// Lane L (0..29) owns elements j = 10L..10L+9; .x = row0, .y = row1.
// ---------------------------------------------------------------------------
__global__ void __launch_bounds__(WARPS * 32, 1)
ladmm_main(const float* __restrict__ b, float* __restrict__ out) {
    extern __shared__ float sm[];
    float* sA    = sm;                         // NM*TBL
    float* sHn   = sA + NM * TBL;              // NLAYERS*NM*TBL
    float* sct   = sHn + NLAYERS * NM * TBL;   // NLAYERS*24
    float* sscal = sct + NLAYERS * 24;         // NLAYERS*8
    float* stage = sscal + NLAYERS * 8;        // WARPS*608

    int tid = threadIdx.x;
    for (int i = tid; i < NM * TBL; i += WARPS * 32) sA[i] = g_At[i];
    for (int i = tid; i < NLAYERS * NM * TBL; i += WARPS * 32) sHn[i] = (&g_Hn[0][0])[i];
    for (int i = tid; i < NLAYERS * 24; i += WARPS * 32) sct[i] = (&g_ct[0][0])[i];
    for (int i = tid; i < NLAYERS * 8; i += WARPS * 32) sscal[i] = (&g_scal[0][0])[i];
    __syncthreads();

    int wid = tid >> 5, lane = tid & 31;
    int base13 = lane * 13;
    int j0 = lane * 10;
    int lm1 = (lane + 29) % 30;
    int lp1 = (lane + 1) % 30;

    const float2 neg1 = make_float2(-1.f, -1.f);
    float* wstage = stage + wid * 608;

    #pragma unroll 1
    for (int rit = 0; rit < RPW; rit++) {
        int pairIdx = blockIdx.x * (WARPS * RPW) + wid * RPW + rit;
        size_t row0 = (size_t)pairIdx * 2;

        // --- b rows (18 contiguous floats) -> bm[m] packed pairs
        float bv = (lane < 2 * NM) ? b[(size_t)pairIdx * (2 * NM) + lane] : 0.f;
        float2 bm[9];
        #pragma unroll
        for (int m = 0; m < 9; m++)
            bm[m] = make_float2(__shfl_sync(FULLMASK, bv, m),
                                __shfl_sync(FULLMASK, bv, 9 + m));

        // --- bA[t] = sum_m bm[m] * A[m][j0+t]
        float2 bA[10];
        #pragma unroll
        for (int t = 0; t < 10; t++) {
            float2 acc = f2mul(bm[0], dup(sA[0 * TBL + base13 + t]));
            #pragma unroll
            for (int m = 1; m < 9; m++)
                acc = f2fma(bm[m], dup(sA[m * TBL + base13 + t]), acc);
            bA[t] = acc;
        }

        float2 x[10], eta[10], tau[10];
        #pragma unroll
        for (int t = 0; t < 10; t++) {
            x[t] = make_float2(1.f, 1.f);
            eta[t] = make_float2(0.f, 0.f);
            tau[t] = make_float2(0.f, 0.f);
        }

        #pragma unroll 1
        for (int l = 0; l < NLAYERS; l++) {
            const float* sc = sscal + l * 8;
            float gs = sc[0], als = sc[1], lamg = sc[2], invgs = sc[3], invals = sc[4];
            float2 g2 = dup(gs), al2 = dup(als), invg2 = dup(invgs), inval2 = dup(invals);
            const float* ctab = sct + l * 24;
            const float* sHl = sHn + l * (NM * TBL);

            // --- residual r = bA + al*w - tau + g*u - eta
            float2 xm1 = shfl2(x[9], lm1);
            float2 r[10];
            #pragma unroll
            for (int t = 0; t < 10; t++) {
                float2 xp = (t == 0) ? xm1 : x[t - 1];
                float2 v = f2fma(neg1, x[t], xp);          // xp - x
                v = f2fma(eta[t], invg2, v);
                float2 u; u.x = softt(v.x, lamg); u.y = softt(v.y, lamg);
                float2 w = f2fma(tau[t], inval2, x[t]);
                w.x = fmaxf(w.x, 0.f); w.y = fmaxf(w.y, 0.f);
                float2 s = f2fma(neg1, tau[t], bA[t]);
                s = f2fma(al2, w, s);
                s = f2fma(g2, u, s);
                r[t] = f2fma(neg1, eta[t], s);
            }

            // --- y = C^-1 r : 21-tap circulant conv, window = [lm1 r | r | lp1 r]
            float2 y[10];
            float2 wchunk[10];
            #pragma unroll
            for (int k = 0; k < 10; k++) wchunk[k] = shfl2(r[k], lm1);
            // taps i=0..9 use wm
            {
                float2 c0 = dup(ctab[0]);
                #pragma unroll
                for (int t = 0; t < 10; t++) y[t] = f2mul(c0, wchunk[t]);
            }
            #pragma unroll
            for (int d = 1; d < 10; d++) {
                float2 cd = dup(ctab[d]);
                #pragma unroll
                for (int t = 0; t < 10; t++)
                    if (t + d < 10) y[t] = f2fma(cd, wchunk[t + d], y[t]);
            }
            // taps i=1..19 use own r
            #pragma unroll
            for (int i = 1; i < 20; i++) {
                float2 ci = dup(ctab[i]);
                #pragma unroll
                for (int t = 0; t < 10; t++) {
                    int k = t + i - 10;
                    if (k >= 0 && k < 10) y[t] = f2fma(ci, r[k], y[t]);
                }
            }
            // taps i=11..20 use wp
            #pragma unroll
            for (int k = 0; k < 10; k++) wchunk[k] = shfl2(r[k], lp1);
            #pragma unroll
            for (int i = 11; i < 21; i++) {
                float2 ci = dup(ctab[i]);
                #pragma unroll
                for (int t = 0; t < 10; t++) {
                    int k = t + i - 20;
                    if (k >= 0 && k < 10) y[t] = f2fma(ci, wchunk[k], y[t]);
                }
            }

            // --- pd[m] = sum_j y_j A[m][j]  (zero-padded lanes contribute 0)
            float2 pd[9];
            #pragma unroll
            for (int m = 0; m < 9; m++)
                pd[m] = f2mul(y[0], dup(sA[m * TBL + base13 + 0]));
            #pragma unroll
            for (int t = 1; t < 10; t++) {
                #pragma unroll
                for (int m = 0; m < 9; m++)
                    pd[m] = f2fma(y[t], dup(sA[m * TBL + base13 + t]), pd[m]);
            }
            #pragma unroll
            for (int m = 0; m < 9; m++) pd[m] = bfly_sum(pd[m]);

            // --- xn = y + sum_m pd[m] * Hn[m][j]   (Hn pre-negated)
            float2 xn[10];
            #pragma unroll
            for (int t = 0; t < 10; t++) {
                float2 acc = y[t];
                #pragma unroll
                for (int m = 0; m < 9; m++)
                    acc = f2fma(pd[m], dup(sHl[m * TBL + base13 + t]), acc);
                xn[t] = acc;
            }

            // --- dual updates (recompute u,w from OLD state)
            float2 xnm1 = shfl2(xn[9], lm1);
            float2 xprev_old = xm1;
            #pragma unroll
            for (int t = 0; t < 10; t++) {
                float2 xp = xprev_old;
                xprev_old = x[t];
                float2 xnp = (t == 0) ? xnm1 : xn[t - 1];
                float2 v = f2fma(neg1, x[t], xp);
                v = f2fma(eta[t], invg2, v);
                float2 u; u.x = softt(v.x, lamg); u.y = softt(v.y, lamg);
                float2 w = f2fma(tau[t], inval2, x[t]);
                w.x = fmaxf(w.x, 0.f); w.y = fmaxf(w.y, 0.f);
                float2 d1 = f2fma(neg1, xn[t], xnp);
                d1 = f2fma(neg1, u, d1);
                eta[t] = f2fma(g2, d1, eta[t]);
                float2 d2 = f2fma(neg1, w, xn[t]);
                tau[t] = f2fma(al2, d2, tau[t]);
                x[t] = xn[t];
            }
        }

        // --- store both rows, coalesced float4 via smem staging
        if (lane < 30) {
            #pragma unroll
            for (int t = 0; t < 10; t++) {
                wstage[j0 + t]       = x[t].x;
                wstage[304 + j0 + t] = x[t].y;
            }
        }
        __syncwarp();
        {
            const float4* st4 = reinterpret_cast<const float4*>(wstage);
            float4* out4 = reinterpret_cast<float4*>(out);
            size_t o0 = row0 * (N / 4);
            for (int idx = lane; idx < N / 4; idx += 32) {
                out4[o0 + idx] = st4[idx];
                out4[o0 + N / 4 + idx] = st4[76 + idx];
            }
        }
        __syncwarp();
    }
}

// ---------------------------------------------------------------------------
extern "C" void kernel_launch(void* const* d_in, const int* in_sizes, int n_in,
                              void* d_out, int out_size) {
    const float* b         = (const float*)d_in[0];
    const float* A         = (const float*)d_in[2];
    const float* gamma_tv  = (const float*)d_in[3];
    const float* lambda_tv = (const float*)d_in[4];
    const float* alpha     = (const float*)d_in[5];
    float* out = (float*)d_out;

    pre_A_kernel<<<(NM * TBL + 255) / 256, 256>>>(A);
    pre_layer_kernel<<<NLAYERS, 256>>>(A, gamma_tv, lambda_tv, alpha);

    size_t smembytes = (size_t)(NM * TBL * (1 + NLAYERS)
                                + NLAYERS * 24 + NLAYERS * 8
                                + WARPS * 608) * sizeof(float);
    cudaFuncSetAttribute(ladmm_main,
                         cudaFuncAttributeMaxDynamicSharedMemorySize,
                         (int)smembytes);
    int grid = BATCH / (2 * WARPS * RPW);
    ladmm_main<<<grid, WARPS * 32, smembytes>>>(b, out);
}